// round 1
// baseline (speedup 1.0000x reference)
#include <cuda_runtime.h>
#include <cstdint>

#define IN_DIM 128
#define HID    64
#define NPB    256          // nodes per block in K1
#define KH     64           // K handled per pass (2 passes over K=128)
#define HS_STRIDE 65        // padded shared stride for H tile (conflict-free reads)
#define W1_STRIDE 72        // padded shared stride for w1 (16B-aligned vector reads)
#define K3_CHUNK 256

#define SMEM_BYTES ((NPB*HS_STRIDE + IN_DIM*W1_STRIDE + NPB) * 4)

// ---------------- scratch (static device globals; no allocation) ----------------
__device__ float    g_s[1100032];      // per-node score, then exp value
__device__ float    g_denom[1048576];  // per-segment softmax denominator
__device__ unsigned g_maxu[1048576];   // per-segment max (order-preserving uint encoding)
__device__ int      g_is64;            // batch dtype flag

// ---------------- helpers ----------------
__device__ __forceinline__ unsigned enc_f(float f) {
    unsigned u = __float_as_uint(f);
    return (u & 0x80000000u) ? ~u : (u | 0x80000000u);
}
__device__ __forceinline__ float dec_f(unsigned u) {
    return (u & 0x80000000u) ? __uint_as_float(u & 0x7fffffffu) : __uint_as_float(~u);
}
__device__ __forceinline__ int getb(const void* bp, int i) {
    if (g_is64) return (int)((const long long*)bp)[i];
    return ((const int*)bp)[i];
}
__device__ __forceinline__ unsigned long long pack2(float x, float y) {
    unsigned long long r;
    asm("mov.b64 %0, {%1, %2};" : "=l"(r) : "r"(__float_as_uint(x)), "r"(__float_as_uint(y)));
    return r;
}
__device__ __forceinline__ float2 unpack2(unsigned long long v) {
    unsigned lo, hi;
    asm("mov.b64 {%0, %1}, %2;" : "=r"(lo), "=r"(hi) : "l"(v));
    return make_float2(__uint_as_float(lo), __uint_as_float(hi));
}
// packed f32x2 FMA (FFMA2) — 2x fp32 throughput vs scalar FFMA on sm_103a
#define FMA2(acc, a, b) asm("fma.rn.f32x2 %0, %1, %2, %0;" : "+l"(acc) : "l"(a), "l"(b))

// ---------------- K-detect: is batch int64 or int32? ----------------
__global__ void kdetect(const void* __restrict__ batch, int N, int G) {
    __shared__ int bad;
    if (threadIdx.x == 0) bad = 0;
    __syncthreads();
    const long long* b64 = (const long long*)batch;
    int half = N >> 1;                      // safe range under either dtype
    int last = (half > 1) ? (half - 1) : 0;
    for (int t = threadIdx.x; t < 2048; t += 256) {
        long long idx = (long long)t * last / 2047;
        long long v = b64[idx];
        if (v < 0 || v >= (long long)G) bad = 1;   // benign race
    }
    __syncthreads();
    if (threadIdx.x == 0) g_is64 = bad ? 0 : 1;
}

// ---------------- K0: zero outputs + per-segment state ----------------
__global__ void k0(float* __restrict__ out, int outSize, int G) {
    int i = blockIdx.x * blockDim.x + threadIdx.x;
    if (i < outSize) out[i] = 0.f;
    if (i < G) { g_denom[i] = 0.f; g_maxu[i] = 0u; }
}

// ---------------- K1: s = w2 . tanh(H w1^T), + segment max ----------------
// 256 threads, 256-node x 64-hid tile, per-thread 8 nodes x 8 hid, f32x2 accs.
__global__ __launch_bounds__(256, 2)
void k1(const float* __restrict__ H, const float* __restrict__ w1,
        const float* __restrict__ w2, const void* __restrict__ batch, int N) {
    extern __shared__ float sm[];
    float* Hs   = sm;                            // [NPB][HS_STRIDE]
    float* w1s  = sm + NPB * HS_STRIDE;          // [128][W1_STRIDE] (k-major)
    float* s_sh = w1s + IN_DIM * W1_STRIDE;      // [NPB]

    const int tid = threadIdx.x;
    const int tn  = tid & 31;      // node lane
    const int th  = tid >> 5;      // hid group (warp id), h = th*8 .. th*8+7
    const int n0  = blockIdx.x * NPB;

    // transpose w1 [64][128] -> w1s[k][h] (one-time, coalesced global reads)
    for (int idx = tid; idx < HID * IN_DIM; idx += 256) {
        int h = idx >> 7, k = idx & 127;
        w1s[k * W1_STRIDE + h] = w1[idx];
    }
    s_sh[tid] = 0.f;

    float w2r[8];
#pragma unroll
    for (int p = 0; p < 8; p++) w2r[p] = __ldg(&w2[th * 8 + p]);

    unsigned long long acc[8][4];
#pragma unroll
    for (int j = 0; j < 8; j++)
#pragma unroll
        for (int p = 0; p < 4; p++) acc[j][p] = 0ull;

    const float4* H4 = (const float4*)H;

    for (int pass = 0; pass < 2; pass++) {
        __syncthreads();
        // stage 256 nodes x 64 K-values of H (coalesced float4 global reads)
#pragma unroll
        for (int it = 0; it < 16; ++it) {
            int idx = it * 256 + tid;
            int row = idx >> 4, c4 = idx & 15;
            int gn = n0 + row;
            float4 v = make_float4(0.f, 0.f, 0.f, 0.f);
            if (gn < N) v = H4[(size_t)gn * 32 + pass * 16 + c4];
            float* d = &Hs[row * HS_STRIDE + c4 * 4];
            d[0] = v.x; d[1] = v.y; d[2] = v.z; d[3] = v.w;
        }
        __syncthreads();

        const float* wk = w1s + pass * KH * W1_STRIDE + th * 8;
#pragma unroll 4
        for (int kk = 0; kk < KH; ++kk) {
            unsigned long long hp[8];
#pragma unroll
            for (int j = 0; j < 8; j++) {
                float hv = Hs[(tn + 32 * j) * HS_STRIDE + kk];
                hp[j] = pack2(hv, hv);
            }
            float4 wa = *(const float4*)(wk + kk * W1_STRIDE);
            float4 wb = *(const float4*)(wk + kk * W1_STRIDE + 4);
            unsigned long long wp[4] = { pack2(wa.x, wa.y), pack2(wa.z, wa.w),
                                         pack2(wb.x, wb.y), pack2(wb.z, wb.w) };
#pragma unroll
            for (int j = 0; j < 8; j++)
#pragma unroll
                for (int p = 0; p < 4; p++)
                    FMA2(acc[j][p], hp[j], wp[p]);
        }
    }

    // epilogue: tanh, dot with w2 slice, reduce across hid groups via shared atomics
#pragma unroll
    for (int j = 0; j < 8; j++) {
        float pn = 0.f;
#pragma unroll
        for (int p = 0; p < 4; p++) {
            float2 v = unpack2(acc[j][p]);
            pn += w2r[2 * p] * tanhf(v.x) + w2r[2 * p + 1] * tanhf(v.y);
        }
        atomicAdd(&s_sh[tn + 32 * j], pn);
    }
    __syncthreads();

    // per node: store s, warp-segmented atomicMax into g_maxu (batch sorted)
    {
        int n = tid, gn = n0 + n;
        bool act = gn < N;
        float s = s_sh[n];
        int b = act ? getb(batch, gn) : 0x7fffffff;
        if (act) g_s[gn] = s;
        unsigned em = act ? enc_f(s) : 0u;
        int lane = tid & 31;
#pragma unroll
        for (int d = 1; d < 32; d <<= 1) {
            unsigned v = __shfl_down_sync(0xffffffffu, em, d);
            int b2     = __shfl_down_sync(0xffffffffu, b, d);
            if ((lane + d) < 32 && b2 == b) em = em > v ? em : v;
        }
        int bprev = __shfl_up_sync(0xffffffffu, b, 1);
        if (act && (lane == 0 || bprev != b)) atomicMax(&g_maxu[b], em);
    }
}

// ---------------- K2: e = exp(s - m[b]); segment-sum denominators ----------------
__global__ void k2(const void* __restrict__ batch, int N) {
    int i = blockIdx.x * blockDim.x + threadIdx.x;
    bool act = i < N;
    int lane = threadIdx.x & 31;
    float e = 0.f;
    int b = 0x7fffffff;
    if (act) {
        b = getb(batch, i);
        float m = dec_f(g_maxu[b]);
        e = expf(g_s[i] - m);
        g_s[i] = e;
    }
#pragma unroll
    for (int d = 1; d < 32; d <<= 1) {
        float v = __shfl_down_sync(0xffffffffu, e, d);
        int b2  = __shfl_down_sync(0xffffffffu, b, d);
        if ((lane + d) < 32 && b2 == b) e += v;
    }
    int bprev = __shfl_up_sync(0xffffffffu, b, 1);
    if (act && (lane == 0 || bprev != b)) atomicAdd(&g_denom[b], e);
}

// ---------------- K3: out[b,:] += (e/denom[b]) * H[i,:] ----------------
// 128 threads = 128 features; block processes K3_CHUNK contiguous (sorted) nodes,
// register-accumulates per segment run, emits coalesced atomicAdds at boundaries.
__global__ __launch_bounds__(128)
void k3(const float* __restrict__ H, const void* __restrict__ batch,
        float* __restrict__ out, int N) {
    __shared__ float cf[K3_CHUNK];
    __shared__ int   sg[K3_CHUNK];
    int f  = threadIdx.x;
    int n0 = blockIdx.x * K3_CHUNK;

    for (int t = f; t < K3_CHUNK; t += 128) {
        int i = n0 + t;
        if (i < N) {
            int b = getb(batch, i);
            sg[t] = b;
            cf[t] = g_s[i] / g_denom[b];
        } else {
            sg[t] = -1;
        }
    }
    __syncthreads();

    float acc = 0.f;
    int cur = sg[0];
    if (cur < 0) return;
#pragma unroll 4
    for (int j = 0; j < K3_CHUNK; ++j) {
        int b = sg[j];
        if (b < 0) break;
        if (b != cur) {
            atomicAdd(&out[(size_t)cur * IN_DIM + f], acc);
            acc = 0.f;
            cur = b;
        }
        acc = fmaf(cf[j], __ldg(&H[(size_t)(n0 + j) * IN_DIM + f]), acc);
    }
    atomicAdd(&out[(size_t)cur * IN_DIM + f], acc);
}

// ---------------- launch ----------------
extern "C" void kernel_launch(void* const* d_in, const int* in_sizes, int n_in,
                              void* d_out, int out_size) {
    const float* H  = (const float*)d_in[0];
    const float* w1 = (const float*)d_in[1];
    const float* w2 = (const float*)d_in[2];
    const void*  batch = d_in[3];
    int N = in_sizes[0] / IN_DIM;
    int G = out_size / IN_DIM;
    float* out = (float*)d_out;

    cudaFuncSetAttribute(k1, cudaFuncAttributeMaxDynamicSharedMemorySize, SMEM_BYTES);

    kdetect<<<1, 256>>>(batch, N, G);
    int initN = out_size > G ? out_size : G;
    k0<<<(initN + 255) / 256, 256>>>(out, out_size, G);
    k1<<<(N + NPB - 1) / NPB, 256, SMEM_BYTES>>>(H, w1, w2, batch, N);
    k2<<<(N + 255) / 256, 256>>>(batch, N);
    k3<<<(N + K3_CHUNK - 1) / K3_CHUNK, 128>>>(H, batch, out, N);
}